// round 1
// baseline (speedup 1.0000x reference)
#include <cuda_runtime.h>

#define BS   2048
#define SEQ  288
#define TSTEPS 288
#define HID  64
#define NH   8
#define DH   8
#define DSZ  29
#define G3   192
#define VPITCH 68   // 68 floats/row: 68%8==4 -> conflict-free LDS.128 across lanes

// shared memory layout (float offsets)
#define VAL_OFF  0
#define WIH_OFF  19584              // 288*68
#define X_OFF    (WIH_OFF + 5568)   // 25152, double buffer 2*32
#define H_OFF    (X_OFF + 64)       // 25216
#define GX_OFF   (H_OFF + 64)       // 25280
#define GH_OFF   (GX_OFF + 192)     // 25472
#define CTX_OFF  (GH_OFF + 192)     // 25664
#define WK_OFF   (CTX_OFF + 64)     // 25728
#define BK_OFF   (WK_OFF + 64)      // 25792
#define OUTS_OFF (BK_OFF + 8)       // 25800
#define SMEM_FLOATS 25808

__global__ __launch_bounds__(256, 2)
void decoder_persist_kernel(const float* __restrict__ xdec,
                            const float* __restrict__ enc,
                            const float* __restrict__ hid,
                            const float* __restrict__ Wih,
                            const float* __restrict__ Whh,
                            const float* __restrict__ bih,
                            const float* __restrict__ bhh,
                            const float* __restrict__ Wk,
                            const float* __restrict__ bk,
                            const float* __restrict__ W1,
                            const float* __restrict__ b1,
                            const float* __restrict__ W2,
                            const float* __restrict__ b2,
                            float* __restrict__ out)
{
    extern __shared__ float sm[];
    const int tid  = threadIdx.x;
    const int warp = tid >> 5;
    const int lane = tid & 31;
    const int b    = blockIdx.x;
    const unsigned FULL = 0xffffffffu;

    // ------- per-thread register-resident weights (roles are disjoint -> one array) -------
    float wreg[64];
    float ba = 0.f, bb = 0.f, b2r = 0.f;
    if (tid < G3) {
        const float4* wp = reinterpret_cast<const float4*>(Whh + tid * HID);
#pragma unroll
        for (int k = 0; k < 16; ++k) {
            float4 v = wp[k];
            wreg[4*k+0] = v.x; wreg[4*k+1] = v.y; wreg[4*k+2] = v.z; wreg[4*k+3] = v.w;
        }
        ba = bih[tid]; bb = bhh[tid];
    } else if (warp == 6) {
        const float4* wp = reinterpret_cast<const float4*>(W1 + lane * HID);
#pragma unroll
        for (int k = 0; k < 16; ++k) {
            float4 v = wp[k];
            wreg[4*k+0] = v.x; wreg[4*k+1] = v.y; wreg[4*k+2] = v.z; wreg[4*k+3] = v.w;
        }
        ba = b1[lane]; bb = W2[lane]; b2r = b2[0];
    }

    // ------- SMEM init -------
    // val[s][c] = enc[s][b][c], row pitch VPITCH
    for (int idx = tid; idx < SEQ * (HID/4); idx += 256) {
        int s = idx >> 4, c4 = idx & 15;
        float4 v = reinterpret_cast<const float4*>(enc + ((size_t)s * BS + b) * HID)[c4];
        *reinterpret_cast<float4*>(&sm[VAL_OFF + s * VPITCH + 4 * c4]) = v;
    }
    for (int idx = tid; idx < G3 * DSZ; idx += 256) sm[WIH_OFF + idx] = Wih[idx];
    if (tid < HID)  sm[H_OFF + tid] = hid[(size_t)b * HID + tid];
    if (tid < DSZ)  sm[X_OFF + tid] = xdec[(size_t)b * (TSTEPS + 1) * DSZ + tid];
    if (tid < 64)   sm[WK_OFF + tid] = Wk[tid];
    if (tid < 8)    sm[BK_OFF + tid] = bk[tid];
    if (tid == 0)   sm[OUTS_OFF] = xdec[(size_t)b * (TSTEPS + 1) * DSZ + 28];

    // prefetch x row for step 1 into registers (warp 7)
    float xv_pre = 0.f;
    if (warp == 7 && lane < 28)
        xv_pre = xdec[((size_t)b * (TSTEPS + 1) + 1) * DSZ + lane];

    __syncthreads();

    for (int t = 0; t < TSTEPS; ++t) {
        const int cur = t & 1, nxt = cur ^ 1;

        // ================= PHASE A =================
        if (tid < G3) {
            // gx partial (k=0..27; k=28 term added in gate phase) + gh (full)
            float accx = ba, acch = bb;
            const float4* x4 = reinterpret_cast<const float4*>(&sm[X_OFF + cur * 32]);
            const float*  wr = &sm[WIH_OFF + tid * DSZ];
#pragma unroll
            for (int k = 0; k < 7; ++k) {
                float4 xv = x4[k];
                accx = fmaf(wr[4*k+0], xv.x, accx);
                accx = fmaf(wr[4*k+1], xv.y, accx);
                accx = fmaf(wr[4*k+2], xv.z, accx);
                accx = fmaf(wr[4*k+3], xv.w, accx);
            }
            const float4* h4 = reinterpret_cast<const float4*>(&sm[H_OFF]);
#pragma unroll
            for (int k = 0; k < 16; ++k) {
                float4 hv = h4[k];
                acch = fmaf(wreg[4*k+0], hv.x, acch);
                acch = fmaf(wreg[4*k+1], hv.y, acch);
                acch = fmaf(wreg[4*k+2], hv.z, acch);
                acch = fmaf(wreg[4*k+3], hv.w, acch);
            }
            sm[GX_OFF + tid] = accx;
            sm[GH_OFF + tid] = acch;
        } else if (warp == 6) {
            // output MLP for step t-1 (overlapped with GRU of step t)
            if (t > 0) {
                float y = ba;
#pragma unroll
                for (int k = 0; k < 64; ++k)
                    y = fmaf(wreg[k], sm[CTX_OFF + k], y);
                float p = fmaxf(y, 0.f) * bb;
#pragma unroll
                for (int off = 16; off >= 1; off >>= 1)
                    p += __shfl_xor_sync(FULL, p, off);
                if (lane == 0) {
                    float o = p + b2r;
                    out[(size_t)b * TSTEPS + (t - 1)] = o;
                    sm[OUTS_OFF] = o;
                }
            }
        } else { // warp 7: commit prefetched x row for step t+1, start load for t+2
            if (lane < 28) {
                sm[X_OFF + nxt * 32 + lane] = xv_pre;
                int row = (t + 2 <= TSTEPS) ? (t + 2) : TSTEPS;
                xv_pre = xdec[((size_t)b * (TSTEPS + 1) + row) * DSZ + lane];
            }
        }
        __syncthreads();

        // ================= PHASE B: gates =================
        if (tid < HID) {
            float o   = sm[OUTS_OFF];
            float gr  = sm[GX_OFF + tid]       + sm[WIH_OFF + tid * DSZ + 28] * o          + sm[GH_OFF + tid];
            float gz  = sm[GX_OFF + 64 + tid]  + sm[WIH_OFF + (64 + tid) * DSZ + 28] * o   + sm[GH_OFF + 64 + tid];
            float gn  = sm[GX_OFF + 128 + tid] + sm[WIH_OFF + (128 + tid) * DSZ + 28] * o;
            float ghn = sm[GH_OFF + 128 + tid];
            float r = 1.f / (1.f + __expf(-gr));
            float z = 1.f / (1.f + __expf(-gz));
            float a  = gn + r * ghn;
            float e2 = __expf(2.f * a);
            float nt = 1.f - 2.f / (e2 + 1.f);     // tanh(a)
            float hp = sm[H_OFF + tid];
            sm[H_OFF + tid] = nt + z * (hp - nt);  // (1-z)n + z*h
        }
        __syncthreads();

        // ================= PHASE C: attention (warp = head) =================
        {
            const int h = warp;
            float tmpq = 0.f;
            if (lane < 8) {           // q'[e] = sum_d h_new[h,d]*Wk[d,e]
#pragma unroll
                for (int d = 0; d < 8; ++d)
                    tmpq = fmaf(sm[H_OFF + h * 8 + d], sm[WK_OFF + d * 8 + lane], tmpq);
            } else if (lane == 8) {   // qb = q . bk
#pragma unroll
                for (int d = 0; d < 8; ++d)
                    tmpq = fmaf(sm[H_OFF + h * 8 + d], sm[BK_OFF + d], tmpq);
            }
            float qp[8];
#pragma unroll
            for (int e = 0; e < 8; ++e) qp[e] = __shfl_sync(FULL, tmpq, e);
            float qb = __shfl_sync(FULL, tmpq, 8);

            float wsum = 0.f;
            float c[8];
#pragma unroll
            for (int d = 0; d < 8; ++d) c[d] = 0.f;

            const float* vb = &sm[VAL_OFF + h * 8];
#pragma unroll
            for (int i = 0; i < 9; ++i) {
                int s = lane + (i << 5);
                const float4* vp = reinterpret_cast<const float4*>(vb + s * VPITCH);
                float4 va = vp[0], vv = vp[1];
                float sc = qb;
                sc = fmaf(qp[0], va.x, sc); sc = fmaf(qp[1], va.y, sc);
                sc = fmaf(qp[2], va.z, sc); sc = fmaf(qp[3], va.w, sc);
                sc = fmaf(qp[4], vv.x, sc); sc = fmaf(qp[5], vv.y, sc);
                sc = fmaf(qp[6], vv.z, sc); sc = fmaf(qp[7], vv.w, sc);
                float e = __expf(sc);     // scores bounded -> safe without max-sub
                wsum += e;
                c[0] = fmaf(e, va.x, c[0]); c[1] = fmaf(e, va.y, c[1]);
                c[2] = fmaf(e, va.z, c[2]); c[3] = fmaf(e, va.w, c[3]);
                c[4] = fmaf(e, vv.x, c[4]); c[5] = fmaf(e, vv.y, c[5]);
                c[6] = fmaf(e, vv.z, c[6]); c[7] = fmaf(e, vv.w, c[7]);
            }
#pragma unroll
            for (int off = 16; off >= 1; off >>= 1) {
                wsum += __shfl_xor_sync(FULL, wsum, off);
#pragma unroll
                for (int d = 0; d < 8; ++d)
                    c[d] += __shfl_xor_sync(FULL, c[d], off);
            }
            if (lane == 0) {
                float inv = 1.f / wsum;
#pragma unroll
                for (int d = 0; d < 8; ++d)
                    sm[CTX_OFF + h * 8 + d] = c[d] * inv;
            }
        }
        __syncthreads();
    }

    // final output MLP for step T-1
    if (warp == 6) {
        float y = ba;
#pragma unroll
        for (int k = 0; k < 64; ++k)
            y = fmaf(wreg[k], sm[CTX_OFF + k], y);
        float p = fmaxf(y, 0.f) * bb;
#pragma unroll
        for (int off = 16; off >= 1; off >>= 1)
            p += __shfl_xor_sync(FULL, p, off);
        if (lane == 0)
            out[(size_t)b * TSTEPS + (TSTEPS - 1)] = p + b2r;
    }
}

extern "C" void kernel_launch(void* const* d_in, const int* in_sizes, int n_in,
                              void* d_out, int out_size)
{
    const float* xdec = (const float*)d_in[0];
    const float* enc  = (const float*)d_in[1];
    const float* hidp = (const float*)d_in[2];
    const float* Wih  = (const float*)d_in[3];
    const float* Whh  = (const float*)d_in[4];
    const float* bih  = (const float*)d_in[5];
    const float* bhh  = (const float*)d_in[6];
    const float* Wk   = (const float*)d_in[7];
    const float* bk   = (const float*)d_in[8];
    const float* W1   = (const float*)d_in[9];
    const float* b1   = (const float*)d_in[10];
    const float* W2   = (const float*)d_in[11];
    const float* b2   = (const float*)d_in[12];
    float* out = (float*)d_out;

    const size_t smem = SMEM_FLOATS * sizeof(float);
    cudaFuncSetAttribute(decoder_persist_kernel,
                         cudaFuncAttributeMaxDynamicSharedMemorySize, (int)smem);
    decoder_persist_kernel<<<BS, 256, smem>>>(xdec, enc, hidp, Wih, Whh, bih, bhh,
                                              Wk, bk, W1, b1, W2, b2, out);
}